// round 3
// baseline (speedup 1.0000x reference)
#include <cuda_runtime.h>
#include <cstdint>

// Problem constants (fixed by the dataset)
#define MAXN 10000
#define KNBR 16
#define FDIM 64
#define HDIM 128

// ---------------- scratch (no allocations allowed) ----------------
__device__ int   g_nidx[MAXN * KNBR];
__device__ float g_dsq [MAXN * KNBR];
__device__ int   g_selfi[MAXN];
__device__ float g_esum[MAXN * HDIM];

// ---------------- helpers ----------------
__device__ __forceinline__ unsigned long long pk2(float lo, float hi) {
    unsigned long long r;
    asm("mov.b64 %0, {%1, %2};" : "=l"(r) : "f"(lo), "f"(hi));
    return r;
}
__device__ __forceinline__ void upk2(unsigned long long v, float& lo, float& hi) {
    asm("mov.b64 {%0, %1}, %2;" : "=f"(lo), "=f"(hi) : "l"(v));
}
__device__ __forceinline__ void fma2(unsigned long long& d, unsigned long long a, unsigned long long b) {
    asm("fma.rn.f32x2 %0, %1, %2, %0;" : "+l"(d) : "l"(a), "l"(b));
}
__device__ __forceinline__ float selu_f(float x) {
    const float sc = 1.0507009873554805f;
    const float al = 1.6732632423543772f;
    return x > 0.f ? sc * x : sc * al * expm1f(x);
}

// ---------------- KNN: one warp per row, exact (d2, idx) ordering ----------------
#define KNN_WARPS 8
__global__ void knn_kernel(const float* __restrict__ coords,
                           const int* __restrict__ rs, int nrs, int N,
                           float* __restrict__ out_nidx_f, float* __restrict__ out_d)
{
    __shared__ unsigned long long mg[KNN_WARPS][17 * 32];
    const int w    = threadIdx.x >> 5;
    const int lane = threadIdx.x & 31;
    const int row  = blockIdx.x * KNN_WARPS + w;
    if (row >= N) return;

    int s0 = 0, s1 = N;
    for (int s = 0; s + 1 < nrs; ++s) {
        int a = rs[s], b = rs[s + 1];
        if (a <= row && row < b) { s0 = a; s1 = b; }
    }

    const float xi = coords[row * 3 + 0];
    const float yi = coords[row * 3 + 1];
    const float zi = coords[row * 3 + 2];
    const float ni = __fadd_rn(__fadd_rn(__fmul_rn(xi, xi), __fmul_rn(yi, yi)), __fmul_rn(zi, zi));

    unsigned long long a[17];
#pragma unroll
    for (int t = 0; t < 17; ++t) a[t] = 0xFFFFFFFFFFFFFFFFull;

    for (int j = s0 + lane; j < s1; j += 32) {
        const float xj = coords[j * 3 + 0];
        const float yj = coords[j * 3 + 1];
        const float zj = coords[j * 3 + 2];
        const float nj  = __fadd_rn(__fadd_rn(__fmul_rn(xj, xj), __fmul_rn(yj, yj)), __fmul_rn(zj, zj));
        const float dot = __fadd_rn(__fadd_rn(__fmul_rn(xi, xj), __fmul_rn(yi, yj)), __fmul_rn(zi, zj));
        float d2 = __fadd_rn(__fadd_rn(ni, nj), __fmul_rn(-2.f, dot));
        d2 = fmaxf(d2, 0.f);
        unsigned long long key =
            ((unsigned long long)__float_as_uint(d2) << 32) | (unsigned)j;
        if (key < a[16]) {
            unsigned long long cur = key;
#pragma unroll
            for (int t = 0; t < 17; ++t) {
                if (cur < a[t]) { unsigned long long tmp = a[t]; a[t] = cur; cur = tmp; }
            }
        }
    }

#pragma unroll
    for (int t = 0; t < 17; ++t) mg[w][lane * 17 + t] = a[t];
    __syncwarp();

    int head = 0;
    for (int t = 0; t < 17; ++t) {
        unsigned long long v = mg[w][lane * 17 + head];
        unsigned long long m = v;
#pragma unroll
        for (int off = 16; off >= 1; off >>= 1) {
            unsigned long long o = __shfl_xor_sync(0xffffffffu, m, off);
            if (o < m) m = o;
        }
        unsigned ball = __ballot_sync(0xffffffffu, v == m);
        int win = __ffs(ball) - 1;
        if (lane == win) head++;
        if (lane == 0) {
            unsigned jj = (unsigned)(m & 0xffffffffu);
            float dd = __uint_as_float((unsigned)(m >> 32));
            if (t == 0) {
                g_selfi[row] = (int)jj;
            } else {
                g_nidx[row * KNBR + t - 1] = (int)jj;
                g_dsq [row * KNBR + t - 1] = dd;
                out_nidx_f[row * KNBR + t - 1] = (float)(int)jj;
                out_d    [row * KNBR + t - 1] = dd;
            }
        }
    }
}

// ---------------- block GEMM (f32x2 packed), operands in smem ----------------
// Computes O[m][n0..n0+7] for 128-col output; A [M x kp] (lda), W [kp x 128] smem,
// bias[128] smem, optional SELU. 256 threads: 16x16 grid, RPT rows x 8 cols/thread.
template<int RPT, bool DO_SELU>
__device__ __forceinline__ void gemm_block(const float* __restrict__ A, int lda,
                                           const float* __restrict__ W,
                                           const float* __restrict__ bias,
                                           float* __restrict__ O, int ldo,
                                           int kp, int valid)
{
    const int tx = threadIdx.x & 15;
    const int ty = threadIdx.x >> 4;
    const int n0 = tx * 8;
    const int m0 = ty * RPT;

    unsigned long long acc[RPT][4];
#pragma unroll
    for (int i = 0; i < RPT; ++i)
#pragma unroll
        for (int j = 0; j < 4; ++j)
            acc[i][j] = pk2(bias[n0 + 2 * j], bias[n0 + 2 * j + 1]);

    const float* Ap = A + m0 * lda;
    for (int k = 0; k < kp; k += 4) {
        float4 av[RPT];
#pragma unroll
        for (int i = 0; i < RPT; ++i)
            av[i] = *reinterpret_cast<const float4*>(Ap + i * lda + k);
#pragma unroll
        for (int r = 0; r < 4; ++r) {
            const float* wr = W + (k + r) * 128 + n0;
            ulonglong2 b0 = *reinterpret_cast<const ulonglong2*>(wr);
            ulonglong2 b1 = *reinterpret_cast<const ulonglong2*>(wr + 4);
#pragma unroll
            for (int i = 0; i < RPT; ++i) {
                float a_ = (r == 0) ? av[i].x : (r == 1) ? av[i].y : (r == 2) ? av[i].z : av[i].w;
                unsigned long long aa = pk2(a_, a_);
                fma2(acc[i][0], aa, b0.x);
                fma2(acc[i][1], aa, b0.y);
                fma2(acc[i][2], aa, b1.x);
                fma2(acc[i][3], aa, b1.y);
            }
        }
    }

#pragma unroll
    for (int i = 0; i < RPT; ++i) {
        int row = m0 + i;
        if (row < valid) {
            float o[8];
#pragma unroll
            for (int j = 0; j < 4; ++j) { upk2(acc[i][j], o[2 * j], o[2 * j + 1]); }
            if (DO_SELU) {
#pragma unroll
                for (int j = 0; j < 8; ++j) o[j] = selu_f(o[j]);
            }
            *reinterpret_cast<float4*>(O + row * ldo + n0)     = make_float4(o[0], o[1], o[2], o[3]);
            *reinterpret_cast<float4*>(O + row * ldo + n0 + 4) = make_float4(o[4], o[5], o[6], o[7]);
        }
    }
}

__device__ __forceinline__ void load_w(float* Wb, const float* __restrict__ Wg, int rows, int kp)
{
    const int tid = threadIdx.x;
    const int n4 = (rows * 128) >> 2;
    for (int i = tid; i < n4; i += 256)
        reinterpret_cast<float4*>(Wb)[i] = reinterpret_cast<const float4*>(Wg)[i];
    for (int i = tid; i < (kp - rows) * 128; i += 256)
        Wb[rows * 128 + i] = 0.f;
}

// ---------------- edge kernel: 8 nodes (128 edges) per block ----------------
#define EDGE_SMEM ((128*132*2 + 132*128 + 128*3) * 4)
__global__ void __launch_bounds__(256, 1)
edge_kernel(const float* __restrict__ h, const float* __restrict__ coords,
            const float* __restrict__ We1, const float* __restrict__ be1,
            const float* __restrict__ We2, const float* __restrict__ be2,
            const float* __restrict__ Wc1, const float* __restrict__ bc1,
            const float* __restrict__ Wc2, const float* __restrict__ bc2,
            float* __restrict__ coords_out, int N)
{
    extern __shared__ float sm[];
    float* bufA = sm;                 // 128 x 132
    float* bufB = bufA + 128 * 132;   // 128 x 132
    float* Wb   = bufB + 128 * 132;   // 132 x 128
    float* bias = Wb + 132 * 128;     // 128
    float* wc2  = bias + 128;         // 128
    float* wsh  = wc2 + 128;          // 128

    __shared__ int   sself[8];
    __shared__ int   snb[128];
    __shared__ float sd[128];

    const int tid  = threadIdx.x;
    const int base = blockIdx.x * 8;

    if (tid < 8)  sself[tid] = (base + tid < N) ? g_selfi[base + tid] : 0;
    if (tid < 128) {
        int e = base * KNBR + tid;
        snb[tid] = (e < N * KNBR) ? g_nidx[e] : 0;
        sd[tid]  = (e < N * KNBR) ? g_dsq[e]  : 0.f;
    }
    if (tid < 128) { // zero pad cols of bufB once
        bufB[tid * 132 + 128] = 0.f; bufB[tid * 132 + 129] = 0.f;
        bufB[tid * 132 + 130] = 0.f; bufB[tid * 132 + 131] = 0.f;
    }
    __syncthreads();

    // Build X0: [d | h_self(64) | h_neig(64) | 0 pad]
    for (int i = tid; i < 128 * 132; i += 256) {
        int e = i / 132;
        int c = i - e * 132;
        float v;
        if (c == 0)        v = sd[e];
        else if (c < 65)   v = h[sself[e >> 4] * FDIM + (c - 1)];
        else if (c < 129)  v = h[snb[e] * FDIM + (c - 65)];
        else               v = 0.f;
        bufA[i] = v;
    }
    load_w(Wb, We1, 129, 132);
    if (tid < 128) bias[tid] = be1[tid];
    __syncthreads();

    gemm_block<8, true>(bufA, 132, Wb, bias, bufB, 132, 132, 128);
    __syncthreads();

    load_w(Wb, We2, 128, 132);
    if (tid < 128) bias[tid] = be2[tid];
    __syncthreads();

    gemm_block<8, true>(bufB, 132, Wb, bias, bufA, 132, 132, 128);  // bufA = e (X2)
    __syncthreads();

    load_w(Wb, Wc1, 128, 132);
    if (tid < 128) { bias[tid] = bc1[tid]; wc2[tid] = Wc2[tid]; }
    __syncthreads();

    gemm_block<8, true>(bufA, 132, Wb, bias, bufB, 132, 132, 128);  // bufB = c
    __syncthreads();

    // w[e] = c . W_c2 + b_c2
    if (tid < 128) {
        float acc = bc2[0];
        const float* crow = bufB + tid * 132;
#pragma unroll 8
        for (int k = 0; k < 128; ++k) acc = fmaf(crow[k], wc2[k], acc);
        wsh[tid] = acc;
    }

    // e_sum per node
    for (int i = tid; i < 8 * 128; i += 256) {
        int n = i >> 7, c = i & 127;
        float s = 0.f;
#pragma unroll
        for (int e = 0; e < 16; ++e) s += bufA[(n * 16 + e) * 132 + c];
        if (base + n < N) g_esum[(base + n) * HDIM + c] = s;
    }
    __syncthreads();

    // coords_new = coords + mean_k(coord_diff * w)
    if (tid < 24) {
        int n = tid / 3, d = tid - 3 * n;
        int row = base + n;
        if (row < N) {
            float ci = coords[row * 3 + d];
            float s = 0.f;
#pragma unroll
            for (int k = 0; k < 16; ++k) {
                int j = snb[n * 16 + k];
                s += (ci - coords[j * 3 + d]) * wsh[n * 16 + k];
            }
            coords_out[row * 3 + d] = ci + s * (1.f / 16.f);
        }
    }
}

// ---------------- node kernel: 64 nodes per block ----------------
#define NODE_SMEM ((64*196 + 64*132 + 196*128 + 128) * 4)
__global__ void __launch_bounds__(256, 1)
node_kernel(const float* __restrict__ h,
            const float* __restrict__ Wn1, const float* __restrict__ bn1,
            const float* __restrict__ Wn2, const float* __restrict__ bn2,
            float* __restrict__ outp, int N)
{
    extern __shared__ float sm[];
    float* bufA = sm;                 // 64 x 196
    float* bufB = bufA + 64 * 196;    // 64 x 132
    float* Wb   = bufB + 64 * 132;    // 196 x 128
    float* bias = Wb + 196 * 128;     // 128

    __shared__ int sself[64];
    const int tid  = threadIdx.x;
    const int base = blockIdx.x * 64;

    if (tid < 64) sself[tid] = (base + tid < N) ? g_selfi[base + tid] : 0;
    if (tid < 64) {
        bufB[tid * 132 + 128] = 0.f; bufB[tid * 132 + 129] = 0.f;
        bufB[tid * 132 + 130] = 0.f; bufB[tid * 132 + 131] = 0.f;
    }
    __syncthreads();

    for (int i = tid; i < 64 * 196; i += 256) {
        int r = i / 196;
        int c = i - 196 * r;
        int node = base + r;
        float v = 0.f;
        if (node < N) {
            if (c < 128)      v = g_esum[node * HDIM + c];
            else if (c < 192) v = h[sself[r] * FDIM + (c - 128)];
        }
        bufA[i] = v;
    }
    load_w(Wb, Wn1, 192, 196);
    if (tid < 128) bias[tid] = bn1[tid];
    __syncthreads();

    gemm_block<4, true>(bufA, 196, Wb, bias, bufB, 132, 196, 64);
    __syncthreads();

    load_w(Wb, Wn2, 128, 132);
    if (tid < 128) bias[tid] = bn2[tid];
    __syncthreads();

    int valid = N - base; if (valid > 64) valid = 64;
    gemm_block<4, false>(bufB, 132, Wb, bias, outp + base * HDIM, HDIM, 132, valid);
}

// ---------------- launch ----------------
extern "C" void kernel_launch(void* const* d_in, const int* in_sizes, int n_in,
                              void* d_out, int out_size)
{
    const float* h      = (const float*)d_in[0];
    const float* coords = (const float*)d_in[1];
    const int*   rs     = (const int*)  d_in[2];
    const float* We1 = (const float*)d_in[3];
    const float* be1 = (const float*)d_in[4];
    const float* We2 = (const float*)d_in[5];
    const float* be2 = (const float*)d_in[6];
    const float* Wc1 = (const float*)d_in[7];
    const float* bc1 = (const float*)d_in[8];
    const float* Wc2 = (const float*)d_in[9];
    const float* bc2 = (const float*)d_in[10];
    const float* Wn1 = (const float*)d_in[11];
    const float* bn1 = (const float*)d_in[12];
    const float* Wn2 = (const float*)d_in[13];
    const float* bn2 = (const float*)d_in[14];

    const int N   = in_sizes[1] / 3;
    const int nrs = in_sizes[2];

    float* out        = (float*)d_out;               // [N,128]
    float* coords_out = out + (size_t)N * HDIM;      // [N,3]
    float* out_nidx   = coords_out + (size_t)N * 3;  // [N,16] (as float)
    float* out_d      = out_nidx + (size_t)N * KNBR; // [N,16]

    cudaFuncSetAttribute(edge_kernel, cudaFuncAttributeMaxDynamicSharedMemorySize, EDGE_SMEM);
    cudaFuncSetAttribute(node_kernel, cudaFuncAttributeMaxDynamicSharedMemorySize, NODE_SMEM);

    knn_kernel<<<(N + KNN_WARPS - 1) / KNN_WARPS, 256>>>(coords, rs, nrs, N, out_nidx, out_d);
    edge_kernel<<<(N + 7) / 8, 256, EDGE_SMEM>>>(h, coords,
                                                 We1, be1, We2, be2, Wc1, bc1, Wc2, bc2,
                                                 coords_out, N);
    node_kernel<<<(N + 63) / 64, 256, NODE_SMEM>>>(h, Wn1, bn1, Wn2, bn2, out, N);
}

// round 4
// speedup vs baseline: 1.2170x; 1.2170x over previous
#include <cuda_runtime.h>
#include <cstdint>

// Problem constants (fixed by the dataset)
#define MAXN 10000
#define KNBR 16
#define FDIM 64
#define HDIM 128

typedef unsigned long long u64;

// ---------------- scratch (no allocations allowed) ----------------
__device__ int   g_nidx[MAXN * KNBR];
__device__ float g_dsq [MAXN * KNBR];
__device__ int   g_selfi[MAXN];
__device__ float g_esum[MAXN * HDIM];
__device__ __align__(16) float g_sx[MAXN];
__device__ __align__(16) float g_sy[MAXN];
__device__ __align__(16) float g_sz[MAXN];
__device__ __align__(16) float g_sn[MAXN];

// ---------------- helpers ----------------
__device__ __forceinline__ u64 pk2(float lo, float hi) {
    u64 r;
    asm("mov.b64 %0, {%1, %2};" : "=l"(r) : "f"(lo), "f"(hi));
    return r;
}
__device__ __forceinline__ void upk2(u64 v, float& lo, float& hi) {
    asm("mov.b64 {%0, %1}, %2;" : "=f"(lo), "=f"(hi) : "l"(v));
}
__device__ __forceinline__ void fma2(u64& d, u64 a, u64 b) {
    asm("fma.rn.f32x2 %0, %1, %2, %0;" : "+l"(d) : "l"(a), "l"(b));
}
__device__ __forceinline__ u64 mul2_(u64 a, u64 b) {
    u64 r; asm("mul.rn.f32x2 %0, %1, %2;" : "=l"(r) : "l"(a), "l"(b)); return r;
}
__device__ __forceinline__ u64 fma2_(u64 a, u64 b, u64 c) {
    u64 r; asm("fma.rn.f32x2 %0, %1, %2, %3;" : "=l"(r) : "l"(a), "l"(b), "l"(c)); return r;
}
__device__ __forceinline__ u64 add2_(u64 a, u64 b) {
    u64 r; asm("add.rn.f32x2 %0, %1, %2;" : "=l"(r) : "l"(a), "l"(b)); return r;
}
__device__ __forceinline__ u64 mk_key(float d, int j) {
    u64 k;
    asm("mov.b64 %0, {%1, %2};" : "=l"(k) : "r"(j), "r"(__float_as_uint(d)));
    return k;  // (f32bits(d) << 32) | j
}
__device__ __forceinline__ float selu_f(float x) {
    const float sc = 1.0507009873554805f;
    const float sa = 1.7580993408473766f;  // sc * alpha
    float e   = __expf(x);
    float neg = __fmaf_rn(sa, e, -sa);
    return x > 0.f ? sc * x : neg;
}

// ---------------- prep: SoA coords + norms (FMA chain matches pair dot) ----
__global__ void prep_kernel(const float* __restrict__ coords, int N) {
    int i = blockIdx.x * 256 + threadIdx.x;
    if (i < N) {
        float x = coords[3 * i + 0];
        float y = coords[3 * i + 1];
        float z = coords[3 * i + 2];
        g_sx[i] = x; g_sy[i] = y; g_sz[i] = z;
        // same op order as the packed pair-dot: mul, fma, fma -> self d2 == 0 exact
        g_sn[i] = __fmaf_rn(z, z, __fmaf_rn(y, y, __fmul_rn(x, x)));
    }
}

// ---------------- KNN: one warp per row, f32x2 pairs + threshold prune ------
#define KNN_WARPS 8
#define PH1 10   // phase-1 pair-iterations per lane (640 candidates warp-wide)

__device__ __forceinline__ void ins17(u64* a, u64 key) {
#pragma unroll
    for (int t = 0; t < 17; ++t) {
        if (key < a[t]) { u64 tmp = a[t]; a[t] = key; key = tmp; }
    }
}

__global__ void __launch_bounds__(256)
knn_kernel(const int* __restrict__ rs, int nrs, int N,
           float* __restrict__ out_nidx_f, float* __restrict__ out_d)
{
    __shared__ u64 mg[KNN_WARPS][17 * 32];
    const int w    = threadIdx.x >> 5;
    const int lane = threadIdx.x & 31;
    const int row  = blockIdx.x * KNN_WARPS + w;
    if (row >= N) return;

    int s0 = 0, s1 = N;
    for (int s = 0; s + 1 < nrs; ++s) {
        int a_ = rs[s], b_ = rs[s + 1];
        if (a_ <= row && row < b_) { s0 = a_; s1 = b_; }
    }

    const float xi = g_sx[row], yi = g_sy[row], zi = g_sz[row], ni = g_sn[row];
    const u64 X2  = pk2(xi, xi);
    const u64 Y2  = pk2(yi, yi);
    const u64 Z2  = pk2(zi, zi);
    const u64 NI2 = pk2(ni, ni);
    const u64 M2  = pk2(-2.f, -2.f);

    u64 a[17];
#pragma unroll
    for (int t = 0; t < 17; ++t) a[t] = 0xFFFFFFFFFFFFFFFFull;

    // scalar single-candidate (exact same rounding as packed path)
    auto scalar_one = [&](int j, u64 T, float Tf) {
        float xj = g_sx[j], yj = g_sy[j], zj = g_sz[j], nj = g_sn[j];
        float dot = __fmul_rn(xi, xj);
        dot = __fmaf_rn(yi, yj, dot);
        dot = __fmaf_rn(zi, zj, dot);
        float nn = __fadd_rn(ni, nj);
        float d2 = __fmaf_rn(-2.f, dot, nn);
        d2 = fmaxf(d2, 0.f);
        if (d2 <= Tf) {
            u64 k = mk_key(d2, j);
            if (k < T && k < a[16]) ins17(a, k);
        }
    };

    int jbase = s0;
    if (s0 & 1) {                       // align pair loads to 8B
        if (lane == 0) scalar_one(s0, 0xFFFFFFFFFFFFFFFFull, 3.402823466e+38f);
        jbase = s0 + 1;
    }
    const int cnt   = s1 - jbase;
    const int npair = cnt >> 1;
    const int rem   = cnt & 1;

    int p  = lane;
    int P1 = 32 * PH1; if (P1 > npair) P1 = npair;

    // -------- phase 1: no prune --------
    for (; p < P1; p += 32) {
        int j = jbase + 2 * p;
        u64 XJ = *(const u64*)(g_sx + j);
        u64 YJ = *(const u64*)(g_sy + j);
        u64 ZJ = *(const u64*)(g_sz + j);
        u64 NJ = *(const u64*)(g_sn + j);
        u64 dot = mul2_(X2, XJ);
        dot = fma2_(Y2, YJ, dot);
        dot = fma2_(Z2, ZJ, dot);
        u64 nn = add2_(NI2, NJ);
        u64 D2 = fma2_(M2, dot, nn);
        float d0, d1; upk2(D2, d0, d1);
        d0 = fmaxf(d0, 0.f); d1 = fmaxf(d1, 0.f);
        u64 k0 = mk_key(d0, j);
        u64 k1 = mk_key(d1, j + 1);
        if (k0 < a[16]) ins17(a, k0);
        if (k1 < a[16]) ins17(a, k1);
    }

    // -------- exact warp threshold T = 17th-smallest seen so far --------
    u64 T  = 0xFFFFFFFFFFFFFFFFull;
    float Tf = 3.402823466e+38f;  // FLT_MAX
    if (npair > P1) {
#pragma unroll
        for (int t = 0; t < 17; ++t) mg[w][lane * 17 + t] = a[t];
        __syncwarp();
        int head = 0;
        for (int t = 0; t < 17; ++t) {
            u64 v = mg[w][lane * 17 + head];
            u64 m = v;
#pragma unroll
            for (int off = 16; off >= 1; off >>= 1) {
                u64 o = __shfl_xor_sync(0xffffffffu, m, off);
                if (o < m) m = o;
            }
            unsigned ball = __ballot_sync(0xffffffffu, v == m);
            int win = __ffs(ball) - 1;
            if (lane == win) head++;
            T = m;
        }
        __syncwarp();
        Tf = __uint_as_float((unsigned)(T >> 32));
    }

    // -------- phase 2: pruned --------
    for (; p < npair; p += 32) {
        int j = jbase + 2 * p;
        u64 XJ = *(const u64*)(g_sx + j);
        u64 YJ = *(const u64*)(g_sy + j);
        u64 ZJ = *(const u64*)(g_sz + j);
        u64 NJ = *(const u64*)(g_sn + j);
        u64 dot = mul2_(X2, XJ);
        dot = fma2_(Y2, YJ, dot);
        dot = fma2_(Z2, ZJ, dot);
        u64 nn = add2_(NI2, NJ);
        u64 D2 = fma2_(M2, dot, nn);
        float d0, d1; upk2(D2, d0, d1);
        d0 = fmaxf(d0, 0.f); d1 = fmaxf(d1, 0.f);
        if (d0 <= Tf) {
            u64 k0 = mk_key(d0, j);
            if (k0 < T && k0 < a[16]) ins17(a, k0);
        }
        if (d1 <= Tf) {
            u64 k1 = mk_key(d1, j + 1);
            if (k1 < T && k1 < a[16]) ins17(a, k1);
        }
    }
    if (rem && lane == 0) scalar_one(s1 - 1, T, Tf);

    // -------- final merge + emit --------
#pragma unroll
    for (int t = 0; t < 17; ++t) mg[w][lane * 17 + t] = a[t];
    __syncwarp();

    int head = 0;
    for (int t = 0; t < 17; ++t) {
        u64 v = mg[w][lane * 17 + head];
        u64 m = v;
#pragma unroll
        for (int off = 16; off >= 1; off >>= 1) {
            u64 o = __shfl_xor_sync(0xffffffffu, m, off);
            if (o < m) m = o;
        }
        unsigned ball = __ballot_sync(0xffffffffu, v == m);
        int win = __ffs(ball) - 1;
        if (lane == win) head++;
        if (lane == 0) {
            unsigned jj = (unsigned)(m & 0xffffffffu);
            float dd = __uint_as_float((unsigned)(m >> 32));
            if (t == 0) {
                g_selfi[row] = (int)jj;
            } else {
                g_nidx[row * KNBR + t - 1] = (int)jj;
                g_dsq [row * KNBR + t - 1] = dd;
                out_nidx_f[row * KNBR + t - 1] = (float)(int)jj;
                out_d    [row * KNBR + t - 1] = dd;
            }
        }
    }
}

// ---------------- block GEMM (f32x2 packed), operands in smem ----------------
template<int RPT, bool DO_SELU>
__device__ __forceinline__ void gemm_block(const float* __restrict__ A, int lda,
                                           const float* __restrict__ W,
                                           const float* __restrict__ bias,
                                           float* __restrict__ O, int ldo,
                                           int kp, int valid)
{
    const int tx = threadIdx.x & 15;
    const int ty = threadIdx.x >> 4;
    const int n0 = tx * 8;
    const int m0 = ty * RPT;

    u64 acc[RPT][4];
#pragma unroll
    for (int i = 0; i < RPT; ++i)
#pragma unroll
        for (int j = 0; j < 4; ++j)
            acc[i][j] = pk2(bias[n0 + 2 * j], bias[n0 + 2 * j + 1]);

    const float* Ap = A + m0 * lda;
    for (int k = 0; k < kp; k += 4) {
        float4 av[RPT];
#pragma unroll
        for (int i = 0; i < RPT; ++i)
            av[i] = *reinterpret_cast<const float4*>(Ap + i * lda + k);
#pragma unroll
        for (int r = 0; r < 4; ++r) {
            const float* wr = W + (k + r) * 128 + n0;
            ulonglong2 b0 = *reinterpret_cast<const ulonglong2*>(wr);
            ulonglong2 b1 = *reinterpret_cast<const ulonglong2*>(wr + 4);
#pragma unroll
            for (int i = 0; i < RPT; ++i) {
                float a_ = (r == 0) ? av[i].x : (r == 1) ? av[i].y : (r == 2) ? av[i].z : av[i].w;
                u64 aa = pk2(a_, a_);
                fma2(acc[i][0], aa, b0.x);
                fma2(acc[i][1], aa, b0.y);
                fma2(acc[i][2], aa, b1.x);
                fma2(acc[i][3], aa, b1.y);
            }
        }
    }

#pragma unroll
    for (int i = 0; i < RPT; ++i) {
        int row = m0 + i;
        if (row < valid) {
            float o[8];
#pragma unroll
            for (int j = 0; j < 4; ++j) { upk2(acc[i][j], o[2 * j], o[2 * j + 1]); }
            if (DO_SELU) {
#pragma unroll
                for (int j = 0; j < 8; ++j) o[j] = selu_f(o[j]);
            }
            *reinterpret_cast<float4*>(O + row * ldo + n0)     = make_float4(o[0], o[1], o[2], o[3]);
            *reinterpret_cast<float4*>(O + row * ldo + n0 + 4) = make_float4(o[4], o[5], o[6], o[7]);
        }
    }
}

__device__ __forceinline__ void load_w(float* Wb, const float* __restrict__ Wg, int rows, int kp)
{
    const int tid = threadIdx.x;
    const int n4 = (rows * 128) >> 2;
    for (int i = tid; i < n4; i += 256)
        reinterpret_cast<float4*>(Wb)[i] = reinterpret_cast<const float4*>(Wg)[i];
    for (int i = tid; i < (kp - rows) * 128; i += 256)
        Wb[rows * 128 + i] = 0.f;
}

// ---------------- edge kernel: 8 nodes (128 edges) per block ----------------
#define EDGE_SMEM ((128*132*2 + 132*128 + 128*3) * 4)
__global__ void __launch_bounds__(256, 1)
edge_kernel(const float* __restrict__ h, const float* __restrict__ coords,
            const float* __restrict__ We1, const float* __restrict__ be1,
            const float* __restrict__ We2, const float* __restrict__ be2,
            const float* __restrict__ Wc1, const float* __restrict__ bc1,
            const float* __restrict__ Wc2, const float* __restrict__ bc2,
            float* __restrict__ coords_out, int N)
{
    extern __shared__ float sm[];
    float* bufA = sm;                 // 128 x 132
    float* bufB = bufA + 128 * 132;   // 128 x 132
    float* Wb   = bufB + 128 * 132;   // 132 x 128
    float* bias = Wb + 132 * 128;     // 128
    float* wc2  = bias + 128;         // 128
    float* wsh  = wc2 + 128;          // 128

    __shared__ int   sself[8];
    __shared__ int   snb[128];
    __shared__ float sd[128];

    const int tid  = threadIdx.x;
    const int base = blockIdx.x * 8;

    if (tid < 8)  sself[tid] = (base + tid < N) ? g_selfi[base + tid] : 0;
    if (tid < 128) {
        int e = base * KNBR + tid;
        snb[tid] = (e < N * KNBR) ? g_nidx[e] : 0;
        sd[tid]  = (e < N * KNBR) ? g_dsq[e]  : 0.f;
    }
    if (tid < 128) {
        bufB[tid * 132 + 128] = 0.f; bufB[tid * 132 + 129] = 0.f;
        bufB[tid * 132 + 130] = 0.f; bufB[tid * 132 + 131] = 0.f;
    }
    __syncthreads();

    for (int i = tid; i < 128 * 132; i += 256) {
        int e = i / 132;
        int c = i - e * 132;
        float v;
        if (c == 0)        v = sd[e];
        else if (c < 65)   v = h[sself[e >> 4] * FDIM + (c - 1)];
        else if (c < 129)  v = h[snb[e] * FDIM + (c - 65)];
        else               v = 0.f;
        bufA[i] = v;
    }
    load_w(Wb, We1, 129, 132);
    if (tid < 128) bias[tid] = be1[tid];
    __syncthreads();

    gemm_block<8, true>(bufA, 132, Wb, bias, bufB, 132, 132, 128);
    __syncthreads();

    load_w(Wb, We2, 128, 132);
    if (tid < 128) bias[tid] = be2[tid];
    __syncthreads();

    gemm_block<8, true>(bufB, 132, Wb, bias, bufA, 132, 132, 128);  // bufA = e
    __syncthreads();

    load_w(Wb, Wc1, 128, 132);
    if (tid < 128) { bias[tid] = bc1[tid]; wc2[tid] = Wc2[tid]; }
    __syncthreads();

    gemm_block<8, true>(bufA, 132, Wb, bias, bufB, 132, 132, 128);  // bufB = c
    __syncthreads();

    if (tid < 128) {
        float acc = bc2[0];
        const float* crow = bufB + tid * 132;
#pragma unroll 8
        for (int k = 0; k < 128; ++k) acc = fmaf(crow[k], wc2[k], acc);
        wsh[tid] = acc;
    }

    for (int i = tid; i < 8 * 128; i += 256) {
        int n = i >> 7, c = i & 127;
        float s = 0.f;
#pragma unroll
        for (int e = 0; e < 16; ++e) s += bufA[(n * 16 + e) * 132 + c];
        if (base + n < N) g_esum[(base + n) * HDIM + c] = s;
    }
    __syncthreads();

    if (tid < 24) {
        int n = tid / 3, d = tid - 3 * n;
        int row = base + n;
        if (row < N) {
            float ci = coords[row * 3 + d];
            float s = 0.f;
#pragma unroll
            for (int k = 0; k < 16; ++k) {
                int j = snb[n * 16 + k];
                s += (ci - coords[j * 3 + d]) * wsh[n * 16 + k];
            }
            coords_out[row * 3 + d] = ci + s * (1.f / 16.f);
        }
    }
}

// ---------------- node kernel: 64 nodes per block ----------------
#define NODE_SMEM ((64*196 + 64*132 + 196*128 + 128) * 4)
__global__ void __launch_bounds__(256, 1)
node_kernel(const float* __restrict__ h,
            const float* __restrict__ Wn1, const float* __restrict__ bn1,
            const float* __restrict__ Wn2, const float* __restrict__ bn2,
            float* __restrict__ outp, int N)
{
    extern __shared__ float sm[];
    float* bufA = sm;                 // 64 x 196
    float* bufB = bufA + 64 * 196;    // 64 x 132
    float* Wb   = bufB + 64 * 132;    // 196 x 128
    float* bias = Wb + 196 * 128;     // 128

    __shared__ int sself[64];
    const int tid  = threadIdx.x;
    const int base = blockIdx.x * 64;

    if (tid < 64) sself[tid] = (base + tid < N) ? g_selfi[base + tid] : 0;
    if (tid < 64) {
        bufB[tid * 132 + 128] = 0.f; bufB[tid * 132 + 129] = 0.f;
        bufB[tid * 132 + 130] = 0.f; bufB[tid * 132 + 131] = 0.f;
    }
    __syncthreads();

    for (int i = tid; i < 64 * 196; i += 256) {
        int r = i / 196;
        int c = i - 196 * r;
        int node = base + r;
        float v = 0.f;
        if (node < N) {
            if (c < 128)      v = g_esum[node * HDIM + c];
            else if (c < 192) v = h[sself[r] * FDIM + (c - 128)];
        }
        bufA[i] = v;
    }
    load_w(Wb, Wn1, 192, 196);
    if (tid < 128) bias[tid] = bn1[tid];
    __syncthreads();

    gemm_block<4, true>(bufA, 196, Wb, bias, bufB, 132, 196, 64);
    __syncthreads();

    load_w(Wb, Wn2, 128, 132);
    if (tid < 128) bias[tid] = bn2[tid];
    __syncthreads();

    int valid = N - base; if (valid > 64) valid = 64;
    gemm_block<4, false>(bufB, 132, Wb, bias, outp + base * HDIM, HDIM, 132, valid);
}

// ---------------- launch ----------------
extern "C" void kernel_launch(void* const* d_in, const int* in_sizes, int n_in,
                              void* d_out, int out_size)
{
    const float* h      = (const float*)d_in[0];
    const float* coords = (const float*)d_in[1];
    const int*   rs     = (const int*)  d_in[2];
    const float* We1 = (const float*)d_in[3];
    const float* be1 = (const float*)d_in[4];
    const float* We2 = (const float*)d_in[5];
    const float* be2 = (const float*)d_in[6];
    const float* Wc1 = (const float*)d_in[7];
    const float* bc1 = (const float*)d_in[8];
    const float* Wc2 = (const float*)d_in[9];
    const float* bc2 = (const float*)d_in[10];
    const float* Wn1 = (const float*)d_in[11];
    const float* bn1 = (const float*)d_in[12];
    const float* Wn2 = (const float*)d_in[13];
    const float* bn2 = (const float*)d_in[14];

    const int N   = in_sizes[1] / 3;
    const int nrs = in_sizes[2];

    float* out        = (float*)d_out;               // [N,128]
    float* coords_out = out + (size_t)N * HDIM;      // [N,3]
    float* out_nidx   = coords_out + (size_t)N * 3;  // [N,16] (as float)
    float* out_d      = out_nidx + (size_t)N * KNBR; // [N,16]

    cudaFuncSetAttribute(edge_kernel, cudaFuncAttributeMaxDynamicSharedMemorySize, EDGE_SMEM);
    cudaFuncSetAttribute(node_kernel, cudaFuncAttributeMaxDynamicSharedMemorySize, NODE_SMEM);

    prep_kernel<<<(N + 255) / 256, 256>>>(coords, N);
    knn_kernel<<<(N + KNN_WARPS - 1) / KNN_WARPS, 256>>>(rs, nrs, N, out_nidx, out_d);
    edge_kernel<<<(N + 7) / 8, 256, EDGE_SMEM>>>(h, coords,
                                                 We1, be1, We2, be2, Wc1, bc1, Wc2, bc2,
                                                 coords_out, N);
    node_kernel<<<(N + 63) / 64, 256, NODE_SMEM>>>(h, Wn1, bn1, Wn2, bn2, out, N);
}

// round 5
// speedup vs baseline: 1.4033x; 1.1530x over previous
#include <cuda_runtime.h>
#include <cstdint>

#define MAXN 10000
#define KNBR 16
#define MAXE (MAXN * KNBR)
#define FDIM 64
#define HDIM 128

typedef unsigned long long u64;

// ---------------- scratch (no allocations allowed) ----------------
__device__ int   g_nidx[MAXE];
__device__ float g_dsq [MAXE];
__device__ int   g_selfi[MAXN];
__device__ float g_w[MAXE];
__device__ __align__(16) float g_sx[MAXN];
__device__ __align__(16) float g_sy[MAXN];
__device__ __align__(16) float g_sz[MAXN];
__device__ __align__(16) float g_sn[MAXN];
__device__ __align__(16) float gW1p[144 * 128];
__device__ __align__(16) float gX0 [(size_t)MAXE * 144];
__device__ __align__(16) float gX1 [(size_t)MAXE * 128];
__device__ __align__(16) float gX2 [(size_t)MAXE * 128];
__device__ __align__(16) float gN0 [(size_t)(MAXN + 128) * 192];
__device__ __align__(16) float gXn1[(size_t)(MAXN + 128) * 128];

// ---------------- helpers ----------------
__device__ __forceinline__ u64 pk2(float lo, float hi) {
    u64 r; asm("mov.b64 %0, {%1, %2};" : "=l"(r) : "f"(lo), "f"(hi)); return r;
}
__device__ __forceinline__ void upk2(u64 v, float& lo, float& hi) {
    asm("mov.b64 {%0, %1}, %2;" : "=f"(lo), "=f"(hi) : "l"(v));
}
__device__ __forceinline__ void fma2(u64& d, u64 a, u64 b) {
    asm("fma.rn.f32x2 %0, %1, %2, %0;" : "+l"(d) : "l"(a), "l"(b));
}
__device__ __forceinline__ u64 mul2_(u64 a, u64 b) {
    u64 r; asm("mul.rn.f32x2 %0, %1, %2;" : "=l"(r) : "l"(a), "l"(b)); return r;
}
__device__ __forceinline__ u64 fma2_(u64 a, u64 b, u64 c) {
    u64 r; asm("fma.rn.f32x2 %0, %1, %2, %3;" : "=l"(r) : "l"(a), "l"(b), "l"(c)); return r;
}
__device__ __forceinline__ u64 add2_(u64 a, u64 b) {
    u64 r; asm("add.rn.f32x2 %0, %1, %2;" : "=l"(r) : "l"(a), "l"(b)); return r;
}
__device__ __forceinline__ u64 mk_key(float d, int j) {
    u64 k; asm("mov.b64 %0, {%1, %2};" : "=l"(k) : "r"(j), "r"(__float_as_uint(d)));
    return k;
}
__device__ __forceinline__ float selu_f(float x) {
    const float sc = 1.0507009873554805f;
    const float sa = 1.7580993408473766f;  // sc * alpha
    float e   = __expf(x);
    float neg = __fmaf_rn(sa, e, -sa);
    return x > 0.f ? sc * x : neg;
}
__device__ __forceinline__ void cpa16(uint32_t dst, const float* src) {
    asm volatile("cp.async.cg.shared.global [%0], [%1], 16;" :: "r"(dst), "l"(src));
}

// ---------------- prep: SoA coords + norms ----------------
__global__ void prep_kernel(const float* __restrict__ coords, int N) {
    int i = blockIdx.x * 256 + threadIdx.x;
    if (i < N) {
        float x = coords[3 * i + 0];
        float y = coords[3 * i + 1];
        float z = coords[3 * i + 2];
        g_sx[i] = x; g_sy[i] = y; g_sz[i] = z;
        g_sn[i] = __fmaf_rn(z, z, __fmaf_rn(y, y, __fmul_rn(x, x)));
    }
}

// ---------------- KNN (unchanged from passing round) ----------------
#define KNN_WARPS 8
#define PH1 10

__device__ __forceinline__ void ins17(u64* a, u64 key) {
#pragma unroll
    for (int t = 0; t < 17; ++t) {
        if (key < a[t]) { u64 tmp = a[t]; a[t] = key; key = tmp; }
    }
}

__global__ void __launch_bounds__(256)
knn_kernel(const int* __restrict__ rs, int nrs, int N,
           float* __restrict__ out_nidx_f, float* __restrict__ out_d)
{
    __shared__ u64 mg[KNN_WARPS][17 * 32];
    const int w    = threadIdx.x >> 5;
    const int lane = threadIdx.x & 31;
    const int row  = blockIdx.x * KNN_WARPS + w;
    if (row >= N) return;

    int s0 = 0, s1 = N;
    for (int s = 0; s + 1 < nrs; ++s) {
        int a_ = rs[s], b_ = rs[s + 1];
        if (a_ <= row && row < b_) { s0 = a_; s1 = b_; }
    }

    const float xi = g_sx[row], yi = g_sy[row], zi = g_sz[row], ni = g_sn[row];
    const u64 X2  = pk2(xi, xi);
    const u64 Y2  = pk2(yi, yi);
    const u64 Z2  = pk2(zi, zi);
    const u64 NI2 = pk2(ni, ni);
    const u64 M2  = pk2(-2.f, -2.f);

    u64 a[17];
#pragma unroll
    for (int t = 0; t < 17; ++t) a[t] = 0xFFFFFFFFFFFFFFFFull;

    auto scalar_one = [&](int j, u64 T, float Tf) {
        float xj = g_sx[j], yj = g_sy[j], zj = g_sz[j], nj = g_sn[j];
        float dot = __fmul_rn(xi, xj);
        dot = __fmaf_rn(yi, yj, dot);
        dot = __fmaf_rn(zi, zj, dot);
        float nn = __fadd_rn(ni, nj);
        float d2 = __fmaf_rn(-2.f, dot, nn);
        d2 = fmaxf(d2, 0.f);
        if (d2 <= Tf) {
            u64 k = mk_key(d2, j);
            if (k < T && k < a[16]) ins17(a, k);
        }
    };

    int jbase = s0;
    if (s0 & 1) {
        if (lane == 0) scalar_one(s0, 0xFFFFFFFFFFFFFFFFull, 3.402823466e+38f);
        jbase = s0 + 1;
    }
    const int cnt   = s1 - jbase;
    const int npair = cnt >> 1;
    const int rem   = cnt & 1;

    int p  = lane;
    int P1 = 32 * PH1; if (P1 > npair) P1 = npair;

    for (; p < P1; p += 32) {
        int j = jbase + 2 * p;
        u64 XJ = *(const u64*)(g_sx + j);
        u64 YJ = *(const u64*)(g_sy + j);
        u64 ZJ = *(const u64*)(g_sz + j);
        u64 NJ = *(const u64*)(g_sn + j);
        u64 dot = mul2_(X2, XJ);
        dot = fma2_(Y2, YJ, dot);
        dot = fma2_(Z2, ZJ, dot);
        u64 nn = add2_(NI2, NJ);
        u64 D2 = fma2_(M2, dot, nn);
        float d0, d1; upk2(D2, d0, d1);
        d0 = fmaxf(d0, 0.f); d1 = fmaxf(d1, 0.f);
        u64 k0 = mk_key(d0, j);
        u64 k1 = mk_key(d1, j + 1);
        if (k0 < a[16]) ins17(a, k0);
        if (k1 < a[16]) ins17(a, k1);
    }

    u64 T  = 0xFFFFFFFFFFFFFFFFull;
    float Tf = 3.402823466e+38f;
    if (npair > P1) {
#pragma unroll
        for (int t = 0; t < 17; ++t) mg[w][lane * 17 + t] = a[t];
        __syncwarp();
        int head = 0;
        for (int t = 0; t < 17; ++t) {
            u64 v = mg[w][lane * 17 + head];
            u64 m = v;
#pragma unroll
            for (int off = 16; off >= 1; off >>= 1) {
                u64 o = __shfl_xor_sync(0xffffffffu, m, off);
                if (o < m) m = o;
            }
            unsigned ball = __ballot_sync(0xffffffffu, v == m);
            int win = __ffs(ball) - 1;
            if (lane == win) head++;
            T = m;
        }
        __syncwarp();
        Tf = __uint_as_float((unsigned)(T >> 32));
    }

    for (; p < npair; p += 32) {
        int j = jbase + 2 * p;
        u64 XJ = *(const u64*)(g_sx + j);
        u64 YJ = *(const u64*)(g_sy + j);
        u64 ZJ = *(const u64*)(g_sz + j);
        u64 NJ = *(const u64*)(g_sn + j);
        u64 dot = mul2_(X2, XJ);
        dot = fma2_(Y2, YJ, dot);
        dot = fma2_(Z2, ZJ, dot);
        u64 nn = add2_(NI2, NJ);
        u64 D2 = fma2_(M2, dot, nn);
        float d0, d1; upk2(D2, d0, d1);
        d0 = fmaxf(d0, 0.f); d1 = fmaxf(d1, 0.f);
        if (d0 <= Tf) {
            u64 k0 = mk_key(d0, j);
            if (k0 < T && k0 < a[16]) ins17(a, k0);
        }
        if (d1 <= Tf) {
            u64 k1 = mk_key(d1, j + 1);
            if (k1 < T && k1 < a[16]) ins17(a, k1);
        }
    }
    if (rem && lane == 0) scalar_one(s1 - 1, T, Tf);

#pragma unroll
    for (int t = 0; t < 17; ++t) mg[w][lane * 17 + t] = a[t];
    __syncwarp();

    int head = 0;
    for (int t = 0; t < 17; ++t) {
        u64 v = mg[w][lane * 17 + head];
        u64 m = v;
#pragma unroll
        for (int off = 16; off >= 1; off >>= 1) {
            u64 o = __shfl_xor_sync(0xffffffffu, m, off);
            if (o < m) m = o;
        }
        unsigned ball = __ballot_sync(0xffffffffu, v == m);
        int win = __ffs(ball) - 1;
        if (lane == win) head++;
        if (lane == 0) {
            unsigned jj = (unsigned)(m & 0xffffffffu);
            float dd = __uint_as_float((unsigned)(m >> 32));
            if (t == 0) {
                g_selfi[row] = (int)jj;
            } else {
                g_nidx[row * KNBR + t - 1] = (int)jj;
                g_dsq [row * KNBR + t - 1] = dd;
                out_nidx_f[row * KNBR + t - 1] = (float)(int)jj;
                out_d    [row * KNBR + t - 1] = dd;
            }
        }
    }
}

// ---------------- build kernels ----------------
// permuted+padded W_e1: rows 0..63 <- We1[1..64], 64..127 <- We1[65..128],
// 128 <- We1[0], 129..143 <- 0
__global__ void prep_w1p(const float* __restrict__ We1) {
    int i = blockIdx.x * 256 + threadIdx.x;
    if (i < 144 * 128) {
        int k = i >> 7, n = i & 127;
        float v = 0.f;
        if (k < 64)        v = We1[(1 + k) * 128 + n];
        else if (k < 128)  v = We1[(1 + k) * 128 + n];   // 65+(k-64) == k+1
        else if (k == 128) v = We1[n];
        gW1p[i] = v;
    }
}

// X0[e][0:64]=h_self, [64:128]=h_neig, [128]=d, [129:144]=0   (64 edges/block)
__global__ void build_x0(const float* __restrict__ h, int E) {
    __shared__ int   s_nb[64];
    __shared__ float s_d [64];
    __shared__ int   s_self[4];
    const int base = blockIdx.x * 64;
    const int tid = threadIdx.x;
    if (tid < 64) { s_nb[tid] = g_nidx[base + tid]; s_d[tid] = g_dsq[base + tid]; }
    if (tid < 4)  s_self[tid] = g_selfi[(base >> 4) + tid];
    __syncthreads();
    for (int idx = tid; idx < 64 * 36; idx += 256) {
        int eL = idx / 36;
        int q  = idx - eL * 36;
        float4 v;
        if (q < 16)       v = *(const float4*)(h + (size_t)s_self[eL >> 4] * FDIM + q * 4);
        else if (q < 32)  v = *(const float4*)(h + (size_t)s_nb[eL] * FDIM + (q - 16) * 4);
        else if (q == 32) v = make_float4(s_d[eL], 0.f, 0.f, 0.f);
        else              v = make_float4(0.f, 0.f, 0.f, 0.f);
        *(float4*)(gX0 + (size_t)(base + eL) * 144 + q * 4) = v;
    }
}

// gN0[n][128:192] = h[self(n)]
__global__ void build_n0(const float* __restrict__ h, int N) {
    int idx = blockIdx.x * 256 + threadIdx.x;
    if (idx < N * 16) {
        int n = idx >> 4, q = idx & 15;
        *(float4*)(gN0 + (size_t)n * 192 + 128 + q * 4) =
            *(const float4*)(h + (size_t)g_selfi[n] * FDIM + q * 4);
    }
}

// coords_new = coords + mean_k((c_i - c_j) * w)
__global__ void coords_kernel(const float* __restrict__ coords,
                              float* __restrict__ cout, int N) {
    int n = blockIdx.x * 256 + threadIdx.x;
    if (n < N) {
        float cx = coords[n * 3 + 0];
        float cy = coords[n * 3 + 1];
        float cz = coords[n * 3 + 2];
        float sx = 0.f, sy = 0.f, sz = 0.f;
#pragma unroll
        for (int k = 0; k < 16; ++k) {
            int j = g_nidx[n * 16 + k];
            float wv = g_w[n * 16 + k];
            sx += (cx - coords[j * 3 + 0]) * wv;
            sy += (cy - coords[j * 3 + 1]) * wv;
            sz += (cz - coords[j * 3 + 2]) * wv;
        }
        cout[n * 3 + 0] = cx + sx * 0.0625f;
        cout[n * 3 + 1] = cy + sy * 0.0625f;
        cout[n * 3 + 2] = cz + sz * 0.0625f;
    }
}

// ---------------- staged GEMM: 128 rows x 128 cols per block ----------------
// EPI: 0 = selu+store, 1 = store, 2 = selu+store+esum->gN0, 3 = selu + w-dot only
__device__ __forceinline__ void mma_chunk(const float* __restrict__ As,
                                          const float* __restrict__ Ws,
                                          u64 (&acc)[8][4], int m0, int n0)
{
#pragma unroll
    for (int s = 0; s < 4; ++s) {
        float4 av[8];
#pragma unroll
        for (int i = 0; i < 8; ++i)
            av[i] = *(const float4*)(As + (m0 + i) * 16 + s * 4);
#pragma unroll
        for (int r = 0; r < 4; ++r) {
            const float* wr = Ws + (s * 4 + r) * 128 + n0;
            ulonglong2 b0 = *(const ulonglong2*)wr;
            ulonglong2 b1 = *(const ulonglong2*)(wr + 4);
#pragma unroll
            for (int i = 0; i < 8; ++i) {
                float a_ = (r == 0) ? av[i].x : (r == 1) ? av[i].y : (r == 2) ? av[i].z : av[i].w;
                u64 aa = pk2(a_, a_);
                fma2(acc[i][0], aa, b0.x);
                fma2(acc[i][1], aa, b0.y);
                fma2(acc[i][2], aa, b1.x);
                fma2(acc[i][3], aa, b1.y);
            }
        }
    }
}

template<int KCH, int EPI>
__global__ void __launch_bounds__(256, 2)
gemm_stage(const float* __restrict__ A, int lda,
           const float* __restrict__ Wg, const float* __restrict__ bias,
           float* __restrict__ O, int ldo, int M,
           const float* __restrict__ wc2g, const float* __restrict__ bc2g,
           float* __restrict__ wout)
{
    extern __shared__ float sm[];
    float* Ws   = sm;                       // KCH*16*128
    float* As   = Ws + KCH * 16 * 128;      // 2 * 128*16
    float* sb   = As + 2 * 128 * 16;        // 128
    float* swc2 = sb + 128;                 // 128

    const int tid = threadIdx.x;
    const int tx = tid & 15, ty = tid >> 4;
    const int n0 = tx * 8,   m0 = ty * 8;
    const long row0 = (long)blockIdx.x * 128;

    for (int i = tid; i < KCH * 512; i += 256)
        ((float4*)Ws)[i] = ((const float4*)Wg)[i];
    if (tid < 32) ((float4*)sb)[tid] = ((const float4*)bias)[tid];
    if (EPI == 3) {
        if (tid >= 32 && tid < 64) ((float4*)swc2)[tid - 32] = ((const float4*)wc2g)[tid - 32];
    }

    const uint32_t asu = (uint32_t)__cvta_generic_to_shared(As);
    auto issue = [&](int c, int bufsel) {
        const float* srcbase = A + row0 * lda + c * 16;
        uint32_t d0 = asu + (uint32_t)(bufsel * 2048 * 4);
        int q = tid;          int r = q >> 2, kq = q & 3;
        cpa16(d0 + (uint32_t)((r * 16 + kq * 4) * 4), srcbase + (long)r * lda + kq * 4);
        q = tid + 256;        r = q >> 2; kq = q & 3;
        cpa16(d0 + (uint32_t)((r * 16 + kq * 4) * 4), srcbase + (long)r * lda + kq * 4);
        asm volatile("cp.async.commit_group;");
    };

    issue(0, 0);
    __syncthreads();   // sb/swc2 visible

    u64 acc[8][4];
#pragma unroll
    for (int i = 0; i < 8; ++i)
#pragma unroll
        for (int j = 0; j < 4; ++j)
            acc[i][j] = pk2(sb[n0 + 2 * j], sb[n0 + 2 * j + 1]);

#pragma unroll 1
    for (int c = 0; c < KCH; ++c) {
        if (c + 1 < KCH) {
            issue(c + 1, (c + 1) & 1);
            asm volatile("cp.async.wait_group 1;");
        } else {
            asm volatile("cp.async.wait_group 0;");
        }
        __syncthreads();
        mma_chunk(As + (c & 1) * 2048, Ws + c * 2048, acc, m0, n0);
        __syncthreads();
    }

    // ---------------- epilogue ----------------
    float psum[8];
    if (EPI == 2) {
#pragma unroll
        for (int j = 0; j < 8; ++j) psum[j] = 0.f;
    }

#pragma unroll
    for (int i = 0; i < 8; ++i) {
        float o[8];
#pragma unroll
        for (int j = 0; j < 4; ++j) upk2(acc[i][j], o[2 * j], o[2 * j + 1]);
        if (EPI != 1) {
#pragma unroll
            for (int j = 0; j < 8; ++j) o[j] = selu_f(o[j]);
        }
        long grow = row0 + m0 + i;
        if (EPI == 0 || EPI == 1 || EPI == 2) {
            if (grow < M) {
                *(float4*)(O + grow * ldo + n0)     = make_float4(o[0], o[1], o[2], o[3]);
                *(float4*)(O + grow * ldo + n0 + 4) = make_float4(o[4], o[5], o[6], o[7]);
            }
        }
        if (EPI == 2) {
#pragma unroll
            for (int j = 0; j < 8; ++j) psum[j] += o[j];
        }
        if (EPI == 3) {
            float p = 0.f;
#pragma unroll
            for (int j = 0; j < 8; ++j) p = fmaf(o[j], swc2[n0 + j], p);
            p += __shfl_xor_sync(0xffffffffu, p, 1);
            p += __shfl_xor_sync(0xffffffffu, p, 2);
            p += __shfl_xor_sync(0xffffffffu, p, 4);
            p += __shfl_xor_sync(0xffffffffu, p, 8);
            if (tx == 0) wout[grow] = p + bc2g[0];
        }
    }

    if (EPI == 2) {
        // combine the two ty-halves of each 16-edge node group (same warp, lanes +-16)
#pragma unroll
        for (int j = 0; j < 8; ++j)
            psum[j] += __shfl_xor_sync(0xffffffffu, psum[j], 16);
        if ((ty & 1) == 0) {
            long node = row0 / 16 + (ty >> 1);
            *(float4*)(gN0 + node * 192 + n0)     = make_float4(psum[0], psum[1], psum[2], psum[3]);
            *(float4*)(gN0 + node * 192 + n0 + 4) = make_float4(psum[4], psum[5], psum[6], psum[7]);
        }
    }
}

// ---------------- launch ----------------
extern "C" void kernel_launch(void* const* d_in, const int* in_sizes, int n_in,
                              void* d_out, int out_size)
{
    const float* h      = (const float*)d_in[0];
    const float* coords = (const float*)d_in[1];
    const int*   rs     = (const int*)  d_in[2];
    const float* We1 = (const float*)d_in[3];
    const float* be1 = (const float*)d_in[4];
    const float* We2 = (const float*)d_in[5];
    const float* be2 = (const float*)d_in[6];
    const float* Wc1 = (const float*)d_in[7];
    const float* bc1 = (const float*)d_in[8];
    const float* Wc2 = (const float*)d_in[9];
    const float* bc2 = (const float*)d_in[10];
    const float* Wn1 = (const float*)d_in[11];
    const float* bn1 = (const float*)d_in[12];
    const float* Wn2 = (const float*)d_in[13];
    const float* bn2 = (const float*)d_in[14];

    const int N   = in_sizes[1] / 3;
    const int nrs = in_sizes[2];
    const int E   = N * KNBR;

    float* out        = (float*)d_out;               // [N,128]
    float* coords_out = out + (size_t)N * HDIM;      // [N,3]
    float* out_nidx   = coords_out + (size_t)N * 3;  // [N,16]
    float* out_d      = out_nidx + (size_t)N * KNBR; // [N,16]

    // get device pointers to scratch
    float *pX0, *pX1, *pX2, *pN0, *pXn1, *pW1p, *pw;
    cudaGetSymbolAddress((void**)&pX0,  gX0);
    cudaGetSymbolAddress((void**)&pX1,  gX1);
    cudaGetSymbolAddress((void**)&pX2,  gX2);
    cudaGetSymbolAddress((void**)&pN0,  gN0);
    cudaGetSymbolAddress((void**)&pXn1, gXn1);
    cudaGetSymbolAddress((void**)&pW1p, gW1p);
    cudaGetSymbolAddress((void**)&pw,   g_w);

    const int SM9  = (9  * 2048 + 4096 + 256) * 4;
    const int SM8  = (8  * 2048 + 4096 + 256) * 4;
    const int SM12 = (12 * 2048 + 4096 + 256) * 4;
    cudaFuncSetAttribute(gemm_stage<9, 0>,  cudaFuncAttributeMaxDynamicSharedMemorySize, SM9);
    cudaFuncSetAttribute(gemm_stage<8, 2>,  cudaFuncAttributeMaxDynamicSharedMemorySize, SM8);
    cudaFuncSetAttribute(gemm_stage<8, 3>,  cudaFuncAttributeMaxDynamicSharedMemorySize, SM8);
    cudaFuncSetAttribute(gemm_stage<12, 0>, cudaFuncAttributeMaxDynamicSharedMemorySize, SM12);
    cudaFuncSetAttribute(gemm_stage<8, 1>,  cudaFuncAttributeMaxDynamicSharedMemorySize, SM8);

    prep_kernel<<<(N + 255) / 256, 256>>>(coords, N);
    knn_kernel<<<(N + KNN_WARPS - 1) / KNN_WARPS, 256>>>(rs, nrs, N, out_nidx, out_d);
    prep_w1p<<<72, 256>>>(We1);
    build_x0<<<E / 64, 256>>>(h, E);
    build_n0<<<(N * 16 + 255) / 256, 256>>>(h, N);

    const int eg = (E + 127) / 128;
    const int ng = (N + 127) / 128;

    // edge MLP stages
    gemm_stage<9, 0><<<eg, 256, SM9>>>(pX0, 144, pW1p, be1, pX1, 128, E,
                                       nullptr, nullptr, nullptr);
    gemm_stage<8, 2><<<eg, 256, SM8>>>(pX1, 128, We2, be2, pX2, 128, E,
                                       nullptr, nullptr, nullptr);
    gemm_stage<8, 3><<<eg, 256, SM8>>>(pX2, 128, Wc1, bc1, nullptr, 0, E,
                                       Wc2, bc2, pw);

    coords_kernel<<<(N + 255) / 256, 256>>>(coords, coords_out, N);

    // node MLP stages
    gemm_stage<12, 0><<<ng, 256, SM12>>>(pN0, 192, Wn1, bn1, pXn1, 128, N,
                                         nullptr, nullptr, nullptr);
    gemm_stage<8, 1><<<ng, 256, SM8>>>(pXn1, 128, Wn2, bn2, out, HDIM, N,
                                       nullptr, nullptr, nullptr);
}